// round 5
// baseline (speedup 1.0000x reference)
#include <cuda_runtime.h>

#define TPB 256
#define SCALE 0.17677669529663687f

// ---------------------------------------------------------------------------
// B=2, C=96, D=H=W=64, WS=8 -> N=64 tokens/window, HEADS=3, HD=32
// 3 branches x 8192 windows. One window per 256-thread block, fully fused.
// FFMA2 paired along reduction dim; all hot smem loads are LDS.128 with
// strides chosen so 16B-chunk step is odd mod 8 (bank-conflict floor).
// ---------------------------------------------------------------------------

union f2u { float2 f; unsigned long long u; };
union f4u { float4 v; f2u h[2]; };
__device__ __forceinline__ void fma2(f2u& d, f2u a, f2u b) {
    asm("fma.rn.f32x2 %0, %1, %2, %0;" : "+l"(d.u) : "l"(a.u), "l"(b.u));
}
__device__ __forceinline__ f4u ld4(const float* p) { f4u r; r.v = *(const float4*)p; return r; }

__device__ __forceinline__ int x_off(int br, int b, int c, int s, int p, int q) {
    int d, h, w;
    if (br == 0)      { d = s; h = p; w = q; }   // image=(b,d), spatial (h,w)
    else if (br == 1) { d = q; h = p; w = s; }   // image=(b,w), spatial (h,d)
    else              { d = p; h = s; w = q; }   // image=(b,h), spatial (d,w)
    return (((b * 96 + c) * 64 + d) * 64 + h) * 64 + w;
}

// smem layout (float offsets); total 28836 floats = 112.7 KB -> 2 CTAs/SM
#define XS   0        // [64][100] window input
#define OS   6400     // [64][100] attention output
#define QQ   12800    // [64][32]  q this head (pre-scaled)  (broadcast operand)
#define KK   14848    // [64][36]  k this head               (distinct operand)
#define VT   17152    // [32][64]  v transposed [d][tok]     (broadcast operand)
#define WST  19200    // [96][96]  staged weights [o][c]     (union with AS_)
#define AS_  19200    // [64][68]  scores
#define TB   28416    // [225]     rpb table slice this head
#define INVS 28644    // [96]
#define SHS  28740    // [96]
#define SMEM_FLOATS 28836

template<bool ATOMIC>
__global__ __launch_bounds__(TPB, 2)
void swin_win_kernel(
    const float* __restrict__ x,
    const float* __restrict__ qkv_w, const float* __restrict__ qkv_b,
    const float* __restrict__ proj_w, const float* __restrict__ proj_b,
    const float* __restrict__ rpb_table,
    const float* __restrict__ bn_g, const float* __restrict__ bn_b,
    const float* __restrict__ bn_m, const float* __restrict__ bn_v,
    float* __restrict__ out, int br_base)
{
    extern __shared__ float sm[];
    float* xs   = sm + XS;
    float* os   = sm + OS;
    float* qq   = sm + QQ;
    float* kk   = sm + KK;
    float* vt   = sm + VT;
    float* wst  = sm + WST;
    float* as_  = sm + AS_;
    float* tb   = sm + TB;
    float* invs = sm + INVS;
    float* shs  = sm + SHS;

    const int tid = threadIdx.x;
    const int bid = blockIdx.x;
    const int br  = br_base + (bid >> 13);
    const int wid = bid & 8191;
    const int g   = wid & 127;          // image index inner -> L2 line sharing
    const int win = wid >> 7;
    const int wi  = win >> 3;
    const int wj  = win & 7;
    const int b   = g >> 6;
    const int s   = g & 63;

    if (tid < 96) {
        float inv = bn_g[br * 96 + tid] * rsqrtf(bn_v[br * 96 + tid] + 1e-5f);
        invs[tid] = inv;
        shs[tid]  = bn_b[br * 96 + tid] - bn_m[br * 96 + tid] * inv;
    }

    // load window: xs[tok][c]
    for (int i = tid; i < 6144; i += TPB) {
        int c   = i >> 6;
        int tok = i & 63;
        int p = wi * 8 + (tok >> 3), q = wj * 8 + (tok & 7);
        xs[tok * 100 + c] = x[x_off(br, b, c, s, p, q)];
    }
    __syncthreads();

    // Thread tilings:
    //  GEMM1/proj: to = tid>>4 (6 outs), tn = tid&15 (tokens {tn+16i})
    //              lanes in warp differ in tn -> xs distinct (step 25 chunks),
    //              wst broadcast.
    const int to = tid >> 4;
    const int tn = tid & 15;

    // =================== per head: qkv GEMM -> attention ===================
    for (int h = 0; h < 3; ++h) {
        // stage head weights wst[u][c], u = mat*32 + dim
        for (int i = tid; i < 9216; i += TPB) {
            int u = i / 96, c = i - u * 96;
            int grow = br * 288 + (u >> 5) * 96 + h * 32 + (u & 31);
            wst[u * 96 + c] = qkv_w[grow * 96 + c];
        }
        if (tid < 225) tb[tid] = rpb_table[(br * 225 + tid) * 3 + h];
        __syncthreads();

        // ---- GEMM1: out[tok][u] = xs[tok][:] . w[u][:] + bias --------------
        {
            f2u acc[4][6];
            #pragma unroll
            for (int j = 0; j < 6; ++j) {
                int u = to * 6 + j;
                float bb = qkv_b[br * 288 + (u >> 5) * 96 + h * 32 + (u & 31)];
                #pragma unroll
                for (int i = 0; i < 4; ++i) acc[i][j].f = make_float2(bb, 0.f);
            }
            #pragma unroll 4
            for (int c = 0; c < 96; c += 4) {
                f4u av[4], wv[6];
                #pragma unroll
                for (int i = 0; i < 4; ++i) av[i] = ld4(xs + (tn + 16 * i) * 100 + c);
                #pragma unroll
                for (int j = 0; j < 6; ++j) wv[j] = ld4(wst + (to * 6 + j) * 96 + c);
                #pragma unroll
                for (int i = 0; i < 4; ++i)
                    #pragma unroll
                    for (int j = 0; j < 6; ++j) {
                        fma2(acc[i][j], av[i].h[0], wv[j].h[0]);
                        fma2(acc[i][j], av[i].h[1], wv[j].h[1]);
                    }
            }
            #pragma unroll
            for (int i = 0; i < 4; ++i) {
                int tok = tn + 16 * i;
                #pragma unroll
                for (int j = 0; j < 6; ++j) {
                    int u = to * 6 + j;
                    float r = acc[i][j].f.x + acc[i][j].f.y;
                    if (u < 32)      qq[tok * 32 + u] = r * SCALE;
                    else if (u < 64) kk[tok * 36 + (u - 32)] = r;
                    else             vt[(u - 64) * 64 + tok] = r;
                }
            }
        }
        __syncthreads();

        // ---- scores: s[n][m] = <q_n,k_m> + bias  (q pre-scaled) ------------
        // n = ng+16i (broadcast operand), m = mg+16k (distinct, step 9 chunks)
        {
            const int ng = tid >> 4;
            const int mg = tid & 15;
            f2u sacc[4][4];
            #pragma unroll
            for (int i = 0; i < 4; ++i)
                #pragma unroll
                for (int k = 0; k < 4; ++k) sacc[i][k].f = make_float2(0.f, 0.f);
            #pragma unroll 2
            for (int d = 0; d < 32; d += 4) {
                f4u qv[4], kv[4];
                #pragma unroll
                for (int i = 0; i < 4; ++i) qv[i] = ld4(qq + (ng + 16 * i) * 32 + d);
                #pragma unroll
                for (int k = 0; k < 4; ++k) kv[k] = ld4(kk + (mg + 16 * k) * 36 + d);
                #pragma unroll
                for (int i = 0; i < 4; ++i)
                    #pragma unroll
                    for (int k = 0; k < 4; ++k) {
                        fma2(sacc[i][k], qv[i].h[0], kv[k].h[0]);
                        fma2(sacc[i][k], qv[i].h[1], kv[k].h[1]);
                    }
            }
            #pragma unroll
            for (int i = 0; i < 4; ++i) {
                int n = ng + 16 * i;
                #pragma unroll
                for (int k = 0; k < 4; ++k) {
                    int m = mg + 16 * k;
                    int dy = (n >> 3) - (m >> 3) + 7;
                    int dx = (n & 7) - (m & 7) + 7;
                    as_[n * 68 + m] = sacc[i][k].f.x + sacc[i][k].f.y
                                      + tb[dy * 15 + dx];
                }
            }
        }
        __syncthreads();

        // ---- softmax: 4 lanes per row --------------------------------------
        {
            const int row  = tid >> 2;
            const int lane = tid & 3;
            float* r = as_ + row * 68 + lane * 16;
            f4u v[4];
            #pragma unroll
            for (int t = 0; t < 4; ++t) v[t] = ld4(r + t * 4);
            float mx = -1e30f;
            #pragma unroll
            for (int t = 0; t < 4; ++t) {
                mx = fmaxf(mx, fmaxf(fmaxf(v[t].v.x, v[t].v.y), fmaxf(v[t].v.z, v[t].v.w)));
            }
            mx = fmaxf(mx, __shfl_xor_sync(0xffffffff, mx, 2));
            mx = fmaxf(mx, __shfl_xor_sync(0xffffffff, mx, 1));
            float sum = 0.f;
            #pragma unroll
            for (int t = 0; t < 4; ++t) {
                v[t].v.x = __expf(v[t].v.x - mx); sum += v[t].v.x;
                v[t].v.y = __expf(v[t].v.y - mx); sum += v[t].v.y;
                v[t].v.z = __expf(v[t].v.z - mx); sum += v[t].v.z;
                v[t].v.w = __expf(v[t].v.w - mx); sum += v[t].v.w;
            }
            sum += __shfl_xor_sync(0xffffffff, sum, 2);
            sum += __shfl_xor_sync(0xffffffff, sum, 1);
            float rs = 1.f / sum;
            #pragma unroll
            for (int t = 0; t < 4; ++t) {
                v[t].v.x *= rs; v[t].v.y *= rs; v[t].v.z *= rs; v[t].v.w *= rs;
                *(float4*)(r + t * 4) = v[t].v;
            }
        }
        __syncthreads();

        // ---- out = attn @ v -> os[n][h*32+dd] ------------------------------
        // rows {ng, ng+32} distinct (step 17 chunks), vt broadcast
        {
            const int ng = tid & 31;
            const int dg = tid >> 5;
            f2u oacc[2][4];
            #pragma unroll
            for (int r2 = 0; r2 < 2; ++r2)
                #pragma unroll
                for (int jj = 0; jj < 4; ++jj) oacc[r2][jj].f = make_float2(0.f, 0.f);
            #pragma unroll 2
            for (int m = 0; m < 64; m += 4) {
                f4u a0 = ld4(as_ + ng * 68 + m);
                f4u a1 = ld4(as_ + (ng + 32) * 68 + m);
                f4u vv[4];
                #pragma unroll
                for (int jj = 0; jj < 4; ++jj) vv[jj] = ld4(vt + (dg * 4 + jj) * 64 + m);
                #pragma unroll
                for (int jj = 0; jj < 4; ++jj) {
                    fma2(oacc[0][jj], a0.h[0], vv[jj].h[0]);
                    fma2(oacc[0][jj], a0.h[1], vv[jj].h[1]);
                    fma2(oacc[1][jj], a1.h[0], vv[jj].h[0]);
                    fma2(oacc[1][jj], a1.h[1], vv[jj].h[1]);
                }
            }
            #pragma unroll
            for (int r2 = 0; r2 < 2; ++r2) {
                int n = ng + 32 * r2;
                float4 o;
                o.x = oacc[r2][0].f.x + oacc[r2][0].f.y;
                o.y = oacc[r2][1].f.x + oacc[r2][1].f.y;
                o.z = oacc[r2][2].f.x + oacc[r2][2].f.y;
                o.w = oacc[r2][3].f.x + oacc[r2][3].f.y;
                *(float4*)(os + n * 100 + h * 32 + dg * 4) = o;
            }
        }
        __syncthreads();
    }

    // =================== proj + BN + LeakyReLU + store =====================
    for (int i = tid; i < 9216; i += TPB) {
        int u = i / 96, c = i - u * 96;
        wst[u * 96 + c] = proj_w[(br * 96 + u) * 96 + c];
    }
    __syncthreads();

    {
        f2u acc[4][6];
        #pragma unroll
        for (int j = 0; j < 6; ++j) {
            float bb = proj_b[br * 96 + to * 6 + j];
            #pragma unroll
            for (int i = 0; i < 4; ++i) acc[i][j].f = make_float2(bb, 0.f);
        }
        #pragma unroll 4
        for (int c = 0; c < 96; c += 4) {
            f4u av[4], wv[6];
            #pragma unroll
            for (int i = 0; i < 4; ++i) av[i] = ld4(os + (tn + 16 * i) * 100 + c);
            #pragma unroll
            for (int j = 0; j < 6; ++j) wv[j] = ld4(wst + (to * 6 + j) * 96 + c);
            #pragma unroll
            for (int i = 0; i < 4; ++i)
                #pragma unroll
                for (int j = 0; j < 6; ++j) {
                    fma2(acc[i][j], av[i].h[0], wv[j].h[0]);
                    fma2(acc[i][j], av[i].h[1], wv[j].h[1]);
                }
        }
        #pragma unroll
        for (int i = 0; i < 4; ++i) {
            int tok = tn + 16 * i;
            int p = wi * 8 + (tok >> 3), q = wj * 8 + (tok & 7);
            #pragma unroll
            for (int j = 0; j < 6; ++j) {
                int co = to * 6 + j;
                float r  = acc[i][j].f.x + acc[i][j].f.y;
                float yn = r * invs[co] + shs[co];
                yn = (yn >= 0.f) ? yn : 0.01f * yn;
                int off = x_off(br, b, co, s, p, q);
                if (ATOMIC) atomicAdd(&out[off], yn);
                else        out[off] = yn;
            }
        }
    }
}

extern "C" void kernel_launch(void* const* d_in, const int* in_sizes, int n_in,
                              void* d_out, int out_size)
{
    (void)in_sizes; (void)n_in; (void)out_size;
    const float* x         = (const float*)d_in[0];
    const float* qkv_w     = (const float*)d_in[1];
    const float* qkv_b     = (const float*)d_in[2];
    const float* proj_w    = (const float*)d_in[3];
    const float* proj_b    = (const float*)d_in[4];
    const float* rpb_table = (const float*)d_in[5];
    const float* bn_g      = (const float*)d_in[6];
    const float* bn_b      = (const float*)d_in[7];
    const float* bn_m      = (const float*)d_in[8];
    const float* bn_v      = (const float*)d_in[9];
    float* out = (float*)d_out;

    const int smem = SMEM_FLOATS * 4;
    cudaFuncSetAttribute(swin_win_kernel<false>,
                         cudaFuncAttributeMaxDynamicSharedMemorySize, smem);
    cudaFuncSetAttribute(swin_win_kernel<true>,
                         cudaFuncAttributeMaxDynamicSharedMemorySize, smem);

    // Branch 0: plain stores (full coverage kills 0xAA poison)
    swin_win_kernel<false><<<8192, TPB, smem>>>(
        x, qkv_w, qkv_b, proj_w, proj_b, rpb_table,
        bn_g, bn_b, bn_m, bn_v, out, 0);
    // Branches 1 & 2: accumulate
    swin_win_kernel<true><<<16384, TPB, smem>>>(
        x, qkv_w, qkv_b, proj_w, proj_b, rpb_table,
        bn_g, bn_b, bn_m, bn_v, out, 1);
}

// round 7
// speedup vs baseline: 1.5089x; 1.5089x over previous
#include <cuda_runtime.h>
#include <cuda_bf16.h>

typedef unsigned int u32;

#define TPB 512
#define SCALE 0.17677669529663687f

// ---------------------------------------------------------------------------
// B=2, C=96, D=H=W=64, WS=8, N=64 tok/window, HEADS=3, HD=32.
// 3 branches x 8192 windows; CTA = 2 windows (M=128), 512 threads, 16 warps.
// All GEMMs via mma.sync.m16n8k16 bf16, 3-pass split (hi*hi+hi*lo+lo*hi).
// All operands stored fragment-packed: A-frag = 1 LDS.128, B-frag = 1 LDS.64.
// ---------------------------------------------------------------------------

// Pre-packed weights: [br][mat: h0,h1,h2,proj][part hi/lo][ntile12][kstep6][lane32][2]u32
// mat<3: rows = {q(h) x32 (xSCALE), k(h) x32, v(h) x32}, cols = 96 in-chans.
__device__ unsigned char g_wpk[3 * 4 * 2 * 18432];

__global__ void wprep(const float* __restrict__ qkv_w,
                      const float* __restrict__ proj_w) {
    int i = blockIdx.x * 256 + threadIdx.x;          // 3*4*96*96 = 110592
    if (i >= 110592) return;
    int k = i % 96, n = (i / 96) % 96, mat = (i / 9216) % 4, br = i / 36864;
    float wv;
    if (mat < 3) {
        int sub = n >> 5, dim = n & 31;              // 0=q,1=k,2=v
        wv = qkv_w[(br * 288 + sub * 96 + mat * 32 + dim) * 96 + k];
        if (sub == 0) wv *= SCALE;
    } else {
        wv = proj_w[(br * 96 + n) * 96 + k];
    }
    __nv_bfloat16 hi = __float2bfloat16(wv);
    __nv_bfloat16 lo = __float2bfloat16(wv - __bfloat162float(hi));
    int nt = n >> 3, ks = k >> 4;
    int lane = ((n & 7) << 2) | ((k >> 1) & 3);
    int rb = (k >> 3) & 1;
    size_t base = (size_t)(br * 4 + mat) * 36864;
    size_t off = (size_t)(nt * 6 + ks) * 256 + lane * 8 + rb * 4 + (k & 1) * 2;
    *(__nv_bfloat16*)(g_wpk + base + off)         = hi;
    *(__nv_bfloat16*)(g_wpk + base + 18432 + off) = lo;
}

__device__ __forceinline__ void mma16816(float* c, const uint4 a, const uint2 b) {
    asm volatile("mma.sync.aligned.m16n8k16.row.col.f32.bf16.bf16.f32 "
        "{%0,%1,%2,%3}, {%4,%5,%6,%7}, {%8,%9}, {%0,%1,%2,%3};"
        : "+f"(c[0]), "+f"(c[1]), "+f"(c[2]), "+f"(c[3])
        : "r"(a.x), "r"(a.y), "r"(a.z), "r"(a.w), "r"(b.x), "r"(b.y));
}

__device__ __forceinline__ void packsplit(float v0, float v1, u32& H, u32& L) {
    __nv_bfloat16 h0 = __float2bfloat16(v0);
    __nv_bfloat16 h1 = __float2bfloat16(v1);
    __nv_bfloat16 l0 = __float2bfloat16(v0 - __bfloat162float(h0));
    __nv_bfloat16 l1 = __float2bfloat16(v1 - __bfloat162float(h1));
    H = (u32)*(unsigned short*)&h0 | ((u32)*(unsigned short*)&h1 << 16);
    L = (u32)*(unsigned short*)&l0 | ((u32)*(unsigned short*)&l1 << 16);
}

__device__ __forceinline__ int x_off(int br, int b, int c, int s, int p, int q) {
    int d, h, w;
    if (br == 0)      { d = s; h = p; w = q; }   // image=(b,d), spatial (h,w)
    else if (br == 1) { d = q; h = p; w = s; }   // image=(b,w), spatial (h,d)
    else              { d = p; h = s; w = q; }   // image=(b,h), spatial (d,w)
    return (((b * 96 + c) * 64 + d) * 64 + h) * 64 + w;
}

// smem byte offsets
#define AXO  0        // x packed-A  [part][mt8][ks6][128]u32 : 49152
#define A2O  49152    // attn-out packed-A, same shape        : 49152
#define WO   98304    // weights [part][nt12][ks6][64]u32: 36864 (union: scores f32 [2][64][68] = 34816)
#define QO   135168   // q packed-A [part][win][mt4][ks2][128]: 16384 (union: probs part-hi)
#define KO   151552   // k packed-B [part][win][nt8][ks2][64] : 16384 (union: probs part-lo)
#define VO   167936   // v packed-B [part][win][nt4][ks4][64] : 16384
#define BQO  184320   // 96 f32 (per-head qkv bias)
#define PBO  184704   // 96 f32
#define INVO 185088   // 96 f32
#define SHO  185472   // 96 f32
#define TBO  185856   // 225 f32
#define SMEM_BYTES 186880

template<bool ATOMIC>
__global__ __launch_bounds__(TPB, 1)
void swin_mma_kernel(
    const float* __restrict__ x,
    const float* __restrict__ qkv_b, const float* __restrict__ proj_b,
    const float* __restrict__ rpb_table,
    const float* __restrict__ bn_g, const float* __restrict__ bn_b,
    const float* __restrict__ bn_m, const float* __restrict__ bn_v,
    float* __restrict__ out, int br_base)
{
    extern __shared__ unsigned char smc[];
    float* bqs  = (float*)(smc + BQO);
    float* pbs  = (float*)(smc + PBO);
    float* invs = (float*)(smc + INVO);
    float* shs  = (float*)(smc + SHO);
    float* tb   = (float*)(smc + TBO);

    const int tid = threadIdx.x;
    const int wrp = tid >> 5;
    const int l   = tid & 31;

    const int bid     = blockIdx.x;
    const int br      = br_base + (bid >> 12);
    const int wid12   = bid & 4095;
    const int g       = wid12 & 127;        // image index inner -> L2 sharing
    const int winpair = wid12 >> 7;         // 0..31
    const int b       = g >> 6;
    const int s       = g & 63;

    if (tid < 96) {
        float inv = bn_g[br * 96 + tid] * rsqrtf(bn_v[br * 96 + tid] + 1e-5f);
        invs[tid] = inv;
        shs[tid]  = bn_b[br * 96 + tid] - bn_m[br * 96 + tid] * inv;
        pbs[tid]  = proj_b[br * 96 + tid];
    }

    // ---- load x -> packed-A (split bf16) ----------------------------------
    for (int i = tid; i < 12288; i += TPB) {
        int row = i & 127, c = i >> 7;                 // c 0..95
        int wl = row >> 6, t = row & 63;
        int win = winpair * 2 + wl;
        int p = ((win >> 3) << 3) + (t >> 3), q = ((win & 7) << 3) + (t & 7);
        float v = x[x_off(br, b, c, s, p, q)];
        __nv_bfloat16 hi = __float2bfloat16(v);
        __nv_bfloat16 lo = __float2bfloat16(v - __bfloat162float(hi));
        int mt = row >> 4, rr = row & 15, ks = c >> 4;
        int ln = ((rr & 7) << 2) | ((c >> 1) & 3);
        int rg = (rr >> 3) | (((c >> 3) & 1) << 1);
        int off = (mt * 6 + ks) * 512 + ln * 16 + rg * 4 + (c & 1) * 2;
        *(__nv_bfloat16*)(smc + AXO + off)         = hi;
        *(__nv_bfloat16*)(smc + AXO + 24576 + off) = lo;
    }

    // ======================= per head ======================================
    for (int h = 0; h < 3; ++h) {
        // stage packed weights + bias + rpb table
        {
            const uint4* src = (const uint4*)(g_wpk + (size_t)(br * 4 + h) * 36864);
            uint4* dst = (uint4*)(smc + WO);
            for (int i = tid; i < 2304; i += TPB) dst[i] = src[i];
        }
        if (tid < 96) {
            int sub = tid >> 5, dim = tid & 31;
            float v = qkv_b[br * 288 + sub * 96 + h * 32 + dim];
            if (sub == 0) v *= SCALE;
            bqs[tid] = v;
        }
        if (tid < 225) tb[tid] = rpb_table[(br * 225 + tid) * 3 + h];
        __syncthreads();

        // ---- GEMM1: [128 tok] x [96 outs(q,k,v of head)] x K=96 ------------
        {
            const int mt = wrp & 7, ng = wrp >> 3;
            float acc[6][4];
            #pragma unroll
            for (int j = 0; j < 6; ++j) {
                int c0 = (ng * 6 + j) * 8 + (l & 3) * 2;
                acc[j][0] = bqs[c0]; acc[j][1] = bqs[c0 + 1];
                acc[j][2] = bqs[c0]; acc[j][3] = bqs[c0 + 1];
            }
            #pragma unroll
            for (int ks = 0; ks < 6; ++ks) {
                uint4 ah = *(const uint4*)(smc + AXO + (mt * 6 + ks) * 512 + l * 16);
                uint4 al = *(const uint4*)(smc + AXO + 24576 + (mt * 6 + ks) * 512 + l * 16);
                #pragma unroll
                for (int j = 0; j < 6; ++j) {
                    int nt = ng * 6 + j;
                    uint2 bh = *(const uint2*)(smc + WO + (nt * 6 + ks) * 256 + l * 8);
                    uint2 bl = *(const uint2*)(smc + WO + 18432 + (nt * 6 + ks) * 256 + l * 8);
                    mma16816(acc[j], ah, bh);
                    mma16816(acc[j], ah, bl);
                    mma16816(acc[j], al, bh);
                }
            }
            const int win = mt >> 2, mtw = mt & 3, r0 = l >> 2;
            #pragma unroll
            for (int j = 0; j < 6; ++j) {
                int nt = ng * 6 + j;
                #pragma unroll
                for (int j2 = 0; j2 < 2; ++j2) {
                    float v0 = acc[j][2 * j2], v1 = acc[j][2 * j2 + 1];
                    if (nt < 4) {                         // q -> packed-A
                        u32 H, L; packsplit(v0, v1, H, L);
                        int o = QO + ((win * 4 + mtw) * 2 + (nt >> 1)) * 512
                                + l * 16 + (j2 | ((nt & 1) << 1)) * 4;
                        *(u32*)(smc + o)        = H;
                        *(u32*)(smc + o + 8192) = L;
                    } else if (nt < 8) {                  // k -> packed-B
                        u32 H, L; packsplit(v0, v1, H, L);
                        int ntk = nt - 4;
                        int tok8 = mtw * 2 + j2;
                        int o = KO + ((win * 8 + tok8) * 2 + (ntk >> 1)) * 256
                                + l * 8 + (ntk & 1) * 4;
                        *(u32*)(smc + o)        = H;
                        *(u32*)(smc + o + 8192) = L;
                    } else {                              // v -> packed-B (transposed pairing)
                        int ntv = nt - 8;
                        #pragma unroll
                        for (int t2 = 0; t2 < 2; ++t2) {
                            int d = ntv * 8 + (l & 3) * 2 + t2;
                            float vv = t2 ? v1 : v0;
                            __nv_bfloat16 hi = __float2bfloat16(vv);
                            __nv_bfloat16 lo = __float2bfloat16(vv - __bfloat162float(hi));
                            int o = VO + ((win * 4 + (d >> 3)) * 4 + mtw) * 256
                                    + (((d & 7) << 2) | ((r0 >> 1) & 3)) * 8
                                    + j2 * 4 + (r0 & 1) * 2;
                            *(__nv_bfloat16*)(smc + o)        = hi;
                            *(__nv_bfloat16*)(smc + o + 8192) = lo;
                        }
                    }
                }
            }
        }
        __syncthreads();

        // ---- QK^T: scores + rpb -> f32 in W region --------------------------
        {
            const int win = wrp >> 3, mt = (wrp >> 1) & 3, ng = wrp & 1;
            float acc[4][4];
            #pragma unroll
            for (int j = 0; j < 4; ++j)
                acc[j][0] = acc[j][1] = acc[j][2] = acc[j][3] = 0.f;
            #pragma unroll
            for (int ks = 0; ks < 2; ++ks) {
                uint4 ah = *(const uint4*)(smc + QO + ((win * 4 + mt) * 2 + ks) * 512 + l * 16);
                uint4 al = *(const uint4*)(smc + QO + 8192 + ((win * 4 + mt) * 2 + ks) * 512 + l * 16);
                #pragma unroll
                for (int j = 0; j < 4; ++j) {
                    int nt = ng * 4 + j;
                    uint2 bh = *(const uint2*)(smc + KO + ((win * 8 + nt) * 2 + ks) * 256 + l * 8);
                    uint2 bl = *(const uint2*)(smc + KO + 8192 + ((win * 8 + nt) * 2 + ks) * 256 + l * 8);
                    mma16816(acc[j], ah, bh);
                    mma16816(acc[j], ah, bl);
                    mma16816(acc[j], al, bh);
                }
            }
            float* sc = (float*)(smc + WO) + win * 4352;
            const int r0 = l >> 2;
            #pragma unroll
            for (int j = 0; j < 4; ++j) {
                int m0 = (ng * 4 + j) * 8 + (l & 3) * 2;
                #pragma unroll
                for (int j2 = 0; j2 < 2; ++j2) {
                    int n = mt * 16 + r0 + 8 * j2;
                    int dy = (n >> 3) - (m0 >> 3) + 7;
                    int dx = (n & 7) - (m0 & 7) + 7;
                    float2 o;
                    o.x = acc[j][2 * j2]     + tb[dy * 15 + dx];
                    o.y = acc[j][2 * j2 + 1] + tb[dy * 15 + dx - 1];
                    *(float2*)(sc + n * 68 + m0) = o;
                }
            }
        }
        __syncthreads();

        // ---- softmax (4 lanes/row) -> probs packed-A into Q/K regions -------
        {
            const int row = tid >> 2, l4 = tid & 3;
            const int win = row >> 6, n = row & 63;
            float* r = (float*)(smc + WO) + win * 4352 + n * 68 + l4 * 16;
            float v[16];
            #pragma unroll
            for (int k4 = 0; k4 < 4; ++k4) *(float4*)(v + 4 * k4) = *(float4*)(r + 4 * k4);
            float mx = -1e30f;
            #pragma unroll
            for (int t = 0; t < 16; ++t) mx = fmaxf(mx, v[t]);
            mx = fmaxf(mx, __shfl_xor_sync(0xffffffff, mx, 2));
            mx = fmaxf(mx, __shfl_xor_sync(0xffffffff, mx, 1));
            float sum = 0.f;
            #pragma unroll
            for (int t = 0; t < 16; ++t) { v[t] = __expf(v[t] - mx); sum += v[t]; }
            sum += __shfl_xor_sync(0xffffffff, sum, 2);
            sum += __shfl_xor_sync(0xffffffff, sum, 1);
            float rs = 1.f / sum;
            int mt = n >> 4;
            int lnb = (n & 7) << 2;
            int rbase = (n >> 3) & 1;
            int off0 = ((win * 4 + mt) * 4 + l4) * 512;
            #pragma unroll
            for (int pp = 0; pp < 8; ++pp) {
                u32 H, L;
                packsplit(v[2 * pp] * rs, v[2 * pp + 1] * rs, H, L);
                int o = off0 + (lnb | (pp & 3)) * 16 + (rbase | ((pp >> 2) << 1)) * 4;
                *(u32*)(smc + QO + o) = H;
                *(u32*)(smc + KO + o) = L;
            }
        }
        __syncthreads();

        // ---- AV: attn-out -> A2 packed-A (split bf16) -----------------------
        {
            const int win = wrp >> 3, mt = (wrp >> 1) & 3, ng = wrp & 1;
            float acc[2][4];
            #pragma unroll
            for (int j = 0; j < 2; ++j)
                acc[j][0] = acc[j][1] = acc[j][2] = acc[j][3] = 0.f;
            #pragma unroll
            for (int ks = 0; ks < 4; ++ks) {
                uint4 ah = *(const uint4*)(smc + QO + ((win * 4 + mt) * 4 + ks) * 512 + l * 16);
                uint4 al = *(const uint4*)(smc + KO + ((win * 4 + mt) * 4 + ks) * 512 + l * 16);
                #pragma unroll
                for (int j = 0; j < 2; ++j) {
                    int nt = ng * 2 + j;
                    uint2 bh = *(const uint2*)(smc + VO + ((win * 4 + nt) * 4 + ks) * 256 + l * 8);
                    uint2 bl = *(const uint2*)(smc + VO + 8192 + ((win * 4 + nt) * 4 + ks) * 256 + l * 8);
                    mma16816(acc[j], ah, bh);
                    mma16816(acc[j], ah, bl);
                    mma16816(acc[j], al, bh);
                }
            }
            const int mta = win * 4 + mt;
            #pragma unroll
            for (int j = 0; j < 2; ++j) {
                int nt = ng * 2 + j;
                int kidx = h * 32 + nt * 8 + (l & 3) * 2;
                int ksa = kidx >> 4;
                int rghi = ((kidx >> 3) & 1) << 1;
                #pragma unroll
                for (int j2 = 0; j2 < 2; ++j2) {
                    u32 H, L;
                    packsplit(acc[j][2 * j2], acc[j][2 * j2 + 1], H, L);
                    int o = A2O + (mta * 6 + ksa) * 512 + l * 16 + (j2 | rghi) * 4;
                    *(u32*)(smc + o)         = H;
                    *(u32*)(smc + o + 24576) = L;
                }
            }
        }
        __syncthreads();
    }

    // ======================= proj + BN + LeakyReLU =========================
    {
        const uint4* src = (const uint4*)(g_wpk + (size_t)(br * 4 + 3) * 36864);
        uint4* dst = (uint4*)(smc + WO);
        for (int i = tid; i < 2304; i += TPB) dst[i] = src[i];
    }
    __syncthreads();

    {
        const int mt = wrp & 7, ng = wrp >> 3;
        float acc[6][4];
        #pragma unroll
        for (int j = 0; j < 6; ++j) {
            int c0 = (ng * 6 + j) * 8 + (l & 3) * 2;
            acc[j][0] = pbs[c0]; acc[j][1] = pbs[c0 + 1];
            acc[j][2] = pbs[c0]; acc[j][3] = pbs[c0 + 1];
        }
        #pragma unroll
        for (int ks = 0; ks < 6; ++ks) {
            uint4 ah = *(const uint4*)(smc + A2O + (mt * 6 + ks) * 512 + l * 16);
            uint4 al = *(const uint4*)(smc + A2O + 24576 + (mt * 6 + ks) * 512 + l * 16);
            #pragma unroll
            for (int j = 0; j < 6; ++j) {
                int nt = ng * 6 + j;
                uint2 bh = *(const uint2*)(smc + WO + (nt * 6 + ks) * 256 + l * 8);
                uint2 bl = *(const uint2*)(smc + WO + 18432 + (nt * 6 + ks) * 256 + l * 8);
                mma16816(acc[j], ah, bh);
                mma16816(acc[j], ah, bl);
                mma16816(acc[j], al, bh);
            }
        }
        const int win = mt >> 2, r0 = l >> 2;
        const int winfull = winpair * 2 + win;
        #pragma unroll
        for (int j = 0; j < 6; ++j) {
            int c0 = (ng * 6 + j) * 8 + (l & 3) * 2;
            #pragma unroll
            for (int j2 = 0; j2 < 2; ++j2) {
                int tl = (mt & 3) * 16 + r0 + 8 * j2;
                int p = ((winfull >> 3) << 3) + (tl >> 3);
                int q = ((winfull & 7) << 3) + (tl & 7);
                #pragma unroll
                for (int t2 = 0; t2 < 2; ++t2) {
                    int co = c0 + t2;
                    float v = acc[j][2 * j2 + t2];
                    float yn = v * invs[co] + shs[co];
                    yn = (yn >= 0.f) ? yn : 0.01f * yn;
                    int off = x_off(br, b, co, s, p, q);
                    if (ATOMIC) atomicAdd(&out[off], yn);
                    else        out[off] = yn;
                }
            }
        }
    }
}

extern "C" void kernel_launch(void* const* d_in, const int* in_sizes, int n_in,
                              void* d_out, int out_size)
{
    (void)in_sizes; (void)n_in; (void)out_size;
    const float* x         = (const float*)d_in[0];
    const float* qkv_w     = (const float*)d_in[1];
    const float* qkv_b     = (const float*)d_in[2];
    const float* proj_w    = (const float*)d_in[3];
    const float* proj_b    = (const float*)d_in[4];
    const float* rpb_table = (const float*)d_in[5];
    const float* bn_g      = (const float*)d_in[6];
    const float* bn_b      = (const float*)d_in[7];
    const float* bn_m      = (const float*)d_in[8];
    const float* bn_v      = (const float*)d_in[9];
    float* out = (float*)d_out;

    wprep<<<432, 256>>>(qkv_w, proj_w);

    cudaFuncSetAttribute(swin_mma_kernel<false>,
                         cudaFuncAttributeMaxDynamicSharedMemorySize, SMEM_BYTES);
    cudaFuncSetAttribute(swin_mma_kernel<true>,
                         cudaFuncAttributeMaxDynamicSharedMemorySize, SMEM_BYTES);

    // Branch 0: plain stores (full output coverage kills 0xAA poison)
    swin_mma_kernel<false><<<4096, TPB, SMEM_BYTES>>>(
        x, qkv_b, proj_b, rpb_table, bn_g, bn_b, bn_m, bn_v, out, 0);
    // Branches 1 & 2: accumulate
    swin_mma_kernel<true><<<8192, TPB, SMEM_BYTES>>>(
        x, qkv_b, proj_b, rpb_table, bn_g, bn_b, bn_m, bn_v, out, 1);
}

// round 8
// speedup vs baseline: 1.5985x; 1.0594x over previous
#include <cuda_runtime.h>
#include <cuda_bf16.h>

typedef unsigned int u32;

#define TPB 256
#define SCALE 0.17677669529663687f

// ---------------------------------------------------------------------------
// B=2, C=96, D=H=W=64, WS=8, N=64 tok/window, HEADS=3, HD=32.
// 3 branches x 8192 windows; CTA = 1 window (M=64), 256 threads, 8 warps,
// 2 CTAs/SM. All GEMMs via mma.sync.m16n8k16 bf16, 3-pass split bf16
// (hi*hi + hi*lo + lo*hi). Operands fragment-packed in smem:
// A-frag = 1 LDS.128, B-frag = 1 LDS.64, conflict-free.
// ---------------------------------------------------------------------------

// Pre-packed weights: [br][mat: h0,h1,h2,proj][part hi/lo][nt12][ks6][lane32][2]u32
__device__ unsigned char g_wpk[3 * 4 * 2 * 18432];

__global__ void wprep(const float* __restrict__ qkv_w,
                      const float* __restrict__ proj_w) {
    int i = blockIdx.x * 256 + threadIdx.x;          // 110592 total
    if (i >= 110592) return;
    int k = i % 96, n = (i / 96) % 96, mat = (i / 9216) % 4, br = i / 36864;
    float wv;
    if (mat < 3) {
        int sub = n >> 5, dim = n & 31;              // 0=q,1=k,2=v
        wv = qkv_w[(br * 288 + sub * 96 + mat * 32 + dim) * 96 + k];
        if (sub == 0) wv *= SCALE;
    } else {
        wv = proj_w[(br * 96 + n) * 96 + k];
    }
    __nv_bfloat16 hi = __float2bfloat16(wv);
    __nv_bfloat16 lo = __float2bfloat16(wv - __bfloat162float(hi));
    int nt = n >> 3, ks = k >> 4;
    int lane = ((n & 7) << 2) | ((k >> 1) & 3);
    int rb = (k >> 3) & 1;
    size_t base = (size_t)(br * 4 + mat) * 36864;
    size_t off = (size_t)(nt * 6 + ks) * 256 + lane * 8 + rb * 4 + (k & 1) * 2;
    *(__nv_bfloat16*)(g_wpk + base + off)         = hi;
    *(__nv_bfloat16*)(g_wpk + base + 18432 + off) = lo;
}

__device__ __forceinline__ void mma16816(float* c, const uint4 a, const uint2 b) {
    asm volatile("mma.sync.aligned.m16n8k16.row.col.f32.bf16.bf16.f32 "
        "{%0,%1,%2,%3}, {%4,%5,%6,%7}, {%8,%9}, {%0,%1,%2,%3};"
        : "+f"(c[0]), "+f"(c[1]), "+f"(c[2]), "+f"(c[3])
        : "r"(a.x), "r"(a.y), "r"(a.z), "r"(a.w), "r"(b.x), "r"(b.y));
}

__device__ __forceinline__ void packsplit(float v0, float v1, u32& H, u32& L) {
    __nv_bfloat16 h0 = __float2bfloat16(v0);
    __nv_bfloat16 h1 = __float2bfloat16(v1);
    __nv_bfloat16 l0 = __float2bfloat16(v0 - __bfloat162float(h0));
    __nv_bfloat16 l1 = __float2bfloat16(v1 - __bfloat162float(h1));
    H = (u32)*(unsigned short*)&h0 | ((u32)*(unsigned short*)&h1 << 16);
    L = (u32)*(unsigned short*)&l0 | ((u32)*(unsigned short*)&l1 << 16);
}

__device__ __forceinline__ int x_off(int br, int b, int c, int s, int p, int q) {
    int d, h, w;
    if (br == 0)      { d = s; h = p; w = q; }   // image=(b,d), spatial (h,w)
    else if (br == 1) { d = q; h = p; w = s; }   // image=(b,w), spatial (h,d)
    else              { d = p; h = s; w = q; }   // image=(b,h), spatial (d,w)
    return (((b * 96 + c) * 64 + d) * 64 + h) * 64 + w;
}

// smem byte offsets (per-CTA total 113152 -> 2 CTAs/SM)
#define AXO  0        // x packed-A [2part][4mt][6ks][512B] : 24576 (lo +12288)
#define A2O  24576    // attn-out packed-A, same shape      : 24576 (lo +12288)
#define WO   49152    // weights [2part][12nt][6ks][256B]: 36864 (lo +18432)
                      //   union: scores f32 [64][68] = 17408
#define QO   86016    // q packed-A [2][4mt][2ks][512] : 8192 (lo +4096); probs-hi [4mt][4ks][512]
#define KO   94208    // k packed-B [2][8nt][2ks][256] : 8192 (lo +4096); probs-lo
#define VO   102400   // v packed-B [2][4nt][4ks][256] : 8192 (lo +4096)
#define BQO  110592   // 96 f32
#define PBO  110976   // 96 f32
#define INVO 111360   // 96 f32
#define SHO  111744   // 96 f32
#define TBO  112128   // 225 f32
#define SMEM_BYTES 113152

template<bool ATOMIC>
__global__ __launch_bounds__(TPB, 2)
void swin_mma_kernel(
    const float* __restrict__ x,
    const float* __restrict__ qkv_b, const float* __restrict__ proj_b,
    const float* __restrict__ rpb_table,
    const float* __restrict__ bn_g, const float* __restrict__ bn_b,
    const float* __restrict__ bn_m, const float* __restrict__ bn_v,
    float* __restrict__ out, int br)
{
    extern __shared__ unsigned char smc[];
    float* bqs  = (float*)(smc + BQO);
    float* pbs  = (float*)(smc + PBO);
    float* invs = (float*)(smc + INVO);
    float* shs  = (float*)(smc + SHO);
    float* tb   = (float*)(smc + TBO);

    const int tid = threadIdx.x;
    const int wrp = tid >> 5;
    const int l   = tid & 31;

    const int bid = blockIdx.x;
    const int g   = bid & 127;          // image index inner -> L2 sharing
    const int win = bid >> 7;           // 0..63
    const int wi  = win >> 3;
    const int wj  = win & 7;
    const int b   = g >> 6;
    const int s   = g & 63;

    if (tid < 96) {
        float inv = bn_g[br * 96 + tid] * rsqrtf(bn_v[br * 96 + tid] + 1e-5f);
        invs[tid] = inv;
        shs[tid]  = bn_b[br * 96 + tid] - bn_m[br * 96 + tid] * inv;
        pbs[tid]  = proj_b[br * 96 + tid];
    }

    // ---- load x -> packed-A (split bf16) ----------------------------------
    for (int i = tid; i < 6144; i += TPB) {
        int row = i & 63, c = i >> 6;                 // c 0..95
        int p = wi * 8 + (row >> 3), q = wj * 8 + (row & 7);
        float v = x[x_off(br, b, c, s, p, q)];
        __nv_bfloat16 hi = __float2bfloat16(v);
        __nv_bfloat16 lo = __float2bfloat16(v - __bfloat162float(hi));
        int mt = row >> 4, rr = row & 15, ks = c >> 4;
        int ln = ((rr & 7) << 2) | ((c >> 1) & 3);
        int rg = (rr >> 3) | (((c >> 3) & 1) << 1);
        int off = (mt * 6 + ks) * 512 + ln * 16 + rg * 4 + (c & 1) * 2;
        *(__nv_bfloat16*)(smc + AXO + off)         = hi;
        *(__nv_bfloat16*)(smc + AXO + 12288 + off) = lo;
    }

    // ======================= per head ======================================
    for (int h = 0; h < 3; ++h) {
        // stage packed weights + bias + rpb table
        {
            const uint4* src = (const uint4*)(g_wpk + (size_t)(br * 4 + h) * 36864);
            uint4* dst = (uint4*)(smc + WO);
            for (int i = tid; i < 2304; i += TPB) dst[i] = src[i];
        }
        if (tid < 96) {
            int sub = tid >> 5, dim = tid & 31;
            float v = qkv_b[br * 288 + sub * 96 + h * 32 + dim];
            if (sub == 0) v *= SCALE;
            bqs[tid] = v;
        }
        if (tid < 225) tb[tid] = rpb_table[(br * 225 + tid) * 3 + h];
        __syncthreads();

        // ---- GEMM1: [64 tok] x [96 outs(q,k,v of head)] x K=96 -------------
        {
            const int mt = wrp & 3, ng = wrp >> 2;
            float acc[6][4];
            #pragma unroll
            for (int j = 0; j < 6; ++j) {
                int c0 = (ng * 6 + j) * 8 + (l & 3) * 2;
                acc[j][0] = bqs[c0]; acc[j][1] = bqs[c0 + 1];
                acc[j][2] = bqs[c0]; acc[j][3] = bqs[c0 + 1];
            }
            #pragma unroll
            for (int ks = 0; ks < 6; ++ks) {
                uint4 ah = *(const uint4*)(smc + AXO + (mt * 6 + ks) * 512 + l * 16);
                uint4 al = *(const uint4*)(smc + AXO + 12288 + (mt * 6 + ks) * 512 + l * 16);
                #pragma unroll
                for (int j = 0; j < 6; ++j) {
                    int nt = ng * 6 + j;
                    uint2 bh = *(const uint2*)(smc + WO + (nt * 6 + ks) * 256 + l * 8);
                    uint2 bl = *(const uint2*)(smc + WO + 18432 + (nt * 6 + ks) * 256 + l * 8);
                    mma16816(acc[j], ah, bh);
                    mma16816(acc[j], ah, bl);
                    mma16816(acc[j], al, bh);
                }
            }
            const int r0 = l >> 2;
            #pragma unroll
            for (int j = 0; j < 6; ++j) {
                int nt = ng * 6 + j;
                #pragma unroll
                for (int j2 = 0; j2 < 2; ++j2) {
                    float v0 = acc[j][2 * j2], v1 = acc[j][2 * j2 + 1];
                    if (nt < 4) {                         // q -> packed-A
                        u32 H, L; packsplit(v0, v1, H, L);
                        int o = QO + (mt * 2 + (nt >> 1)) * 512
                                + l * 16 + (j2 | ((nt & 1) << 1)) * 4;
                        *(u32*)(smc + o)        = H;
                        *(u32*)(smc + o + 4096) = L;
                    } else if (nt < 8) {                  // k -> packed-B
                        u32 H, L; packsplit(v0, v1, H, L);
                        int ntk = nt - 4;
                        int tok8 = mt * 2 + j2;
                        int o = KO + (tok8 * 2 + (ntk >> 1)) * 256
                                + l * 8 + (ntk & 1) * 4;
                        *(u32*)(smc + o)        = H;
                        *(u32*)(smc + o + 4096) = L;
                    } else {                              // v -> packed-B (transposed)
                        int ntv = nt - 8;
                        #pragma unroll
                        for (int t2 = 0; t2 < 2; ++t2) {
                            int d = ntv * 8 + (l & 3) * 2 + t2;
                            float vv = t2 ? v1 : v0;
                            __nv_bfloat16 hi = __float2bfloat16(vv);
                            __nv_bfloat16 lo = __float2bfloat16(vv - __bfloat162float(hi));
                            int o = VO + ((d >> 3) * 4 + mt) * 256
                                    + (((d & 7) << 2) | ((r0 >> 1) & 3)) * 8
                                    + j2 * 4 + (r0 & 1) * 2;
                            *(__nv_bfloat16*)(smc + o)        = hi;
                            *(__nv_bfloat16*)(smc + o + 4096) = lo;
                        }
                    }
                }
            }
        }
        __syncthreads();

        // ---- QK^T: scores + rpb -> f32 in W region -------------------------
        {
            const int mt = wrp >> 1, ng = wrp & 1;
            float acc[4][4];
            #pragma unroll
            for (int j = 0; j < 4; ++j)
                acc[j][0] = acc[j][1] = acc[j][2] = acc[j][3] = 0.f;
            #pragma unroll
            for (int ks = 0; ks < 2; ++ks) {
                uint4 ah = *(const uint4*)(smc + QO + (mt * 2 + ks) * 512 + l * 16);
                uint4 al = *(const uint4*)(smc + QO + 4096 + (mt * 2 + ks) * 512 + l * 16);
                #pragma unroll
                for (int j = 0; j < 4; ++j) {
                    int nt = ng * 4 + j;
                    uint2 bh = *(const uint2*)(smc + KO + (nt * 2 + ks) * 256 + l * 8);
                    uint2 bl = *(const uint2*)(smc + KO + 4096 + (nt * 2 + ks) * 256 + l * 8);
                    mma16816(acc[j], ah, bh);
                    mma16816(acc[j], ah, bl);
                    mma16816(acc[j], al, bh);
                }
            }
            float* sc = (float*)(smc + WO);
            const int r0 = l >> 2;
            #pragma unroll
            for (int j = 0; j < 4; ++j) {
                int m0 = (ng * 4 + j) * 8 + (l & 3) * 2;
                #pragma unroll
                for (int j2 = 0; j2 < 2; ++j2) {
                    int n = mt * 16 + r0 + 8 * j2;
                    int dy = (n >> 3) - (m0 >> 3) + 7;
                    int dx = (n & 7) - (m0 & 7) + 7;
                    float2 o;
                    o.x = acc[j][2 * j2]     + tb[dy * 15 + dx];
                    o.y = acc[j][2 * j2 + 1] + tb[dy * 15 + dx - 1];
                    *(float2*)(sc + n * 68 + m0) = o;
                }
            }
        }
        __syncthreads();

        // ---- softmax (4 lanes/row) -> probs packed-A into Q(hi)/K(lo) ------
        {
            const int n = tid >> 2, l4 = tid & 3;
            float* r = (float*)(smc + WO) + n * 68 + l4 * 16;
            float v[16];
            #pragma unroll
            for (int k4 = 0; k4 < 4; ++k4) *(float4*)(v + 4 * k4) = *(float4*)(r + 4 * k4);
            float mx = -1e30f;
            #pragma unroll
            for (int t = 0; t < 16; ++t) mx = fmaxf(mx, v[t]);
            mx = fmaxf(mx, __shfl_xor_sync(0xffffffff, mx, 2));
            mx = fmaxf(mx, __shfl_xor_sync(0xffffffff, mx, 1));
            float sum = 0.f;
            #pragma unroll
            for (int t = 0; t < 16; ++t) { v[t] = __expf(v[t] - mx); sum += v[t]; }
            sum += __shfl_xor_sync(0xffffffff, sum, 2);
            sum += __shfl_xor_sync(0xffffffff, sum, 1);
            float rs = 1.f / sum;
            int mt = n >> 4;
            int lnb = (n & 7) << 2;
            int rbase = (n >> 3) & 1;
            int off0 = (mt * 4 + l4) * 512;
            #pragma unroll
            for (int pp = 0; pp < 8; ++pp) {
                u32 H, L;
                packsplit(v[2 * pp] * rs, v[2 * pp + 1] * rs, H, L);
                int o = off0 + (lnb | (pp & 3)) * 16 + (rbase | ((pp >> 2) << 1)) * 4;
                *(u32*)(smc + QO + o) = H;
                *(u32*)(smc + KO + o) = L;
            }
        }
        __syncthreads();

        // ---- AV: attn-out -> A2 packed-A (split bf16) ----------------------
        {
            const int mt = wrp >> 1, ng = wrp & 1;
            float acc[2][4];
            #pragma unroll
            for (int j = 0; j < 2; ++j)
                acc[j][0] = acc[j][1] = acc[j][2] = acc[j][3] = 0.f;
            #pragma unroll
            for (int ks = 0; ks < 4; ++ks) {
                uint4 ah = *(const uint4*)(smc + QO + (mt * 4 + ks) * 512 + l * 16);
                uint4 al = *(const uint4*)(smc + KO + (mt * 4 + ks) * 512 + l * 16);
                #pragma unroll
                for (int j = 0; j < 2; ++j) {
                    int nt = ng * 2 + j;
                    uint2 bh = *(const uint2*)(smc + VO + (nt * 4 + ks) * 256 + l * 8);
                    uint2 bl = *(const uint2*)(smc + VO + 4096 + (nt * 4 + ks) * 256 + l * 8);
                    mma16816(acc[j], ah, bh);
                    mma16816(acc[j], ah, bl);
                    mma16816(acc[j], al, bh);
                }
            }
            #pragma unroll
            for (int j = 0; j < 2; ++j) {
                int nt = ng * 2 + j;
                int kidx = h * 32 + nt * 8 + (l & 3) * 2;
                int ksa = kidx >> 4;
                int rghi = ((kidx >> 3) & 1) << 1;
                #pragma unroll
                for (int j2 = 0; j2 < 2; ++j2) {
                    u32 H, L;
                    packsplit(acc[j][2 * j2], acc[j][2 * j2 + 1], H, L);
                    int o = A2O + (mt * 6 + ksa) * 512 + l * 16 + (j2 | rghi) * 4;
                    *(u32*)(smc + o)         = H;
                    *(u32*)(smc + o + 12288) = L;
                }
            }
        }
        __syncthreads();
    }

    // ======================= proj + BN + LeakyReLU =========================
    {
        const uint4* src = (const uint4*)(g_wpk + (size_t)(br * 4 + 3) * 36864);
        uint4* dst = (uint4*)(smc + WO);
        for (int i = tid; i < 2304; i += TPB) dst[i] = src[i];
    }
    __syncthreads();

    {
        const int mt = wrp & 3, ng = wrp >> 2;
        float acc[6][4];
        #pragma unroll
        for (int j = 0; j < 6; ++j) {
            int c0 = (ng * 6 + j) * 8 + (l & 3) * 2;
            acc[j][0] = pbs[c0]; acc[j][1] = pbs[c0 + 1];
            acc[j][2] = pbs[c0]; acc[j][3] = pbs[c0 + 1];
        }
        #pragma unroll
        for (int ks = 0; ks < 6; ++ks) {
            uint4 ah = *(const uint4*)(smc + A2O + (mt * 6 + ks) * 512 + l * 16);
            uint4 al = *(const uint4*)(smc + A2O + 12288 + (mt * 6 + ks) * 512 + l * 16);
            #pragma unroll
            for (int j = 0; j < 6; ++j) {
                int nt = ng * 6 + j;
                uint2 bh = *(const uint2*)(smc + WO + (nt * 6 + ks) * 256 + l * 8);
                uint2 bl = *(const uint2*)(smc + WO + 18432 + (nt * 6 + ks) * 256 + l * 8);
                mma16816(acc[j], ah, bh);
                mma16816(acc[j], ah, bl);
                mma16816(acc[j], al, bh);
            }
        }
        const int r0 = l >> 2;
        #pragma unroll
        for (int j = 0; j < 6; ++j) {
            int c0 = (ng * 6 + j) * 8 + (l & 3) * 2;
            #pragma unroll
            for (int j2 = 0; j2 < 2; ++j2) {
                int tl = mt * 16 + r0 + 8 * j2;
                int p = wi * 8 + (tl >> 3);
                int q = wj * 8 + (tl & 7);
                #pragma unroll
                for (int t2 = 0; t2 < 2; ++t2) {
                    int co = c0 + t2;
                    float v = acc[j][2 * j2 + t2];
                    float yn = v * invs[co] + shs[co];
                    yn = (yn >= 0.f) ? yn : 0.01f * yn;
                    int off = x_off(br, b, co, s, p, q);
                    if (ATOMIC) atomicAdd(&out[off], yn);
                    else        out[off] = yn;
                }
            }
        }
    }
}

extern "C" void kernel_launch(void* const* d_in, const int* in_sizes, int n_in,
                              void* d_out, int out_size)
{
    (void)in_sizes; (void)n_in; (void)out_size;
    const float* x         = (const float*)d_in[0];
    const float* qkv_w     = (const float*)d_in[1];
    const float* qkv_b     = (const float*)d_in[2];
    const float* proj_w    = (const float*)d_in[3];
    const float* proj_b    = (const float*)d_in[4];
    const float* rpb_table = (const float*)d_in[5];
    const float* bn_g      = (const float*)d_in[6];
    const float* bn_b      = (const float*)d_in[7];
    const float* bn_m      = (const float*)d_in[8];
    const float* bn_v      = (const float*)d_in[9];
    float* out = (float*)d_out;

    wprep<<<432, 256>>>(qkv_w, proj_w);

    cudaFuncSetAttribute(swin_mma_kernel<false>,
                         cudaFuncAttributeMaxDynamicSharedMemorySize, SMEM_BYTES);
    cudaFuncSetAttribute(swin_mma_kernel<true>,
                         cudaFuncAttributeMaxDynamicSharedMemorySize, SMEM_BYTES);

    // Branch 0: plain stores (full output coverage kills 0xAA poison)
    swin_mma_kernel<false><<<8192, TPB, SMEM_BYTES>>>(
        x, qkv_b, proj_b, rpb_table, bn_g, bn_b, bn_m, bn_v, out, 0);
    // Branches 1 & 2: accumulate
    swin_mma_kernel<true><<<8192, TPB, SMEM_BYTES>>>(
        x, qkv_b, proj_b, rpb_table, bn_g, bn_b, bn_m, bn_v, out, 1);
    swin_mma_kernel<true><<<8192, TPB, SMEM_BYTES>>>(
        x, qkv_b, proj_b, rpb_table, bn_g, bn_b, bn_m, bn_v, out, 2);
}

// round 9
// speedup vs baseline: 2.0363x; 1.2739x over previous
#include <cuda_runtime.h>
#include <cuda_bf16.h>

typedef unsigned int u32;

#define TPB 256
#define SCALE 0.17677669529663687f

// ---------------------------------------------------------------------------
// B=2, C=96, D=H=W=64, WS=8, N=64 tok/window, HEADS=3, HD=32.
// 3 branches x 8192 windows; CTA = 1 window (M=64), 256 threads, 8 warps,
// 2 CTAs/SM. mma.sync.m16n8k16 bf16, 3-pass split bf16.
// Attention is FlashAttention-style: scores/softmax/probs live in registers
// (warp owns a full 16-row block); weight staging for the next matrix is
// overlapped with attention on warps 4-7.
// ---------------------------------------------------------------------------

// Pre-packed weights: [br][mat: h0,h1,h2,proj][part hi/lo][nt12][ks6][lane32][2]u32
__device__ unsigned char g_wpk[3 * 4 * 2 * 18432];
// Expanded rpb bias: [br][h][n][m]
__device__ float g_bias[3 * 3 * 4096];

__global__ void wprep(const float* __restrict__ qkv_w,
                      const float* __restrict__ proj_w,
                      const float* __restrict__ rpb_table,
                      const int* __restrict__ rpb_index) {
    int i = blockIdx.x * 256 + threadIdx.x;          // 147456 total
    if (i < 110592) {
        int k = i % 96, n = (i / 96) % 96, mat = (i / 9216) % 4, br = i / 36864;
        float wv;
        if (mat < 3) {
            int sub = n >> 5, dim = n & 31;          // 0=q,1=k,2=v
            wv = qkv_w[(br * 288 + sub * 96 + mat * 32 + dim) * 96 + k];
            if (sub == 0) wv *= SCALE;
        } else {
            wv = proj_w[(br * 96 + n) * 96 + k];
        }
        __nv_bfloat16 hi = __float2bfloat16(wv);
        __nv_bfloat16 lo = __float2bfloat16(wv - __bfloat162float(hi));
        int nt = n >> 3, ks = k >> 4;
        int lane = ((n & 7) << 2) | ((k >> 1) & 3);
        int rb = (k >> 3) & 1;
        size_t base = (size_t)(br * 4 + mat) * 36864;
        size_t off = (size_t)(nt * 6 + ks) * 256 + lane * 8 + rb * 4 + (k & 1) * 2;
        *(__nv_bfloat16*)(g_wpk + base + off)         = hi;
        *(__nv_bfloat16*)(g_wpk + base + 18432 + off) = lo;
    } else if (i < 147456) {
        int j = i - 110592;                          // 36864 bias entries
        int br = j / 12288;
        int h  = (j >> 12) % 3;
        int nm = j & 4095;
        g_bias[j] = rpb_table[(br * 225 + rpb_index[nm]) * 3 + h];
    }
}

__device__ __forceinline__ void mma16816(float* c, const uint4 a, const uint2 b) {
    asm volatile("mma.sync.aligned.m16n8k16.row.col.f32.bf16.bf16.f32 "
        "{%0,%1,%2,%3}, {%4,%5,%6,%7}, {%8,%9}, {%0,%1,%2,%3};"
        : "+f"(c[0]), "+f"(c[1]), "+f"(c[2]), "+f"(c[3])
        : "r"(a.x), "r"(a.y), "r"(a.z), "r"(a.w), "r"(b.x), "r"(b.y));
}

__device__ __forceinline__ void packsplit(float v0, float v1, u32& H, u32& L) {
    __nv_bfloat16 h0 = __float2bfloat16(v0);
    __nv_bfloat16 h1 = __float2bfloat16(v1);
    __nv_bfloat16 l0 = __float2bfloat16(v0 - __bfloat162float(h0));
    __nv_bfloat16 l1 = __float2bfloat16(v1 - __bfloat162float(h1));
    H = (u32)*(unsigned short*)&h0 | ((u32)*(unsigned short*)&h1 << 16);
    L = (u32)*(unsigned short*)&l0 | ((u32)*(unsigned short*)&l1 << 16);
}

__device__ __forceinline__ int x_off(int br, int b, int c, int s, int p, int q) {
    int d, h, w;
    if (br == 0)      { d = s; h = p; w = q; }   // image=(b,d), spatial (h,w)
    else if (br == 1) { d = q; h = p; w = s; }   // image=(b,w), spatial (h,d)
    else              { d = p; h = s; w = q; }   // image=(b,h), spatial (d,w)
    return (((b * 96 + c) * 64 + d) * 64 + h) * 64 + w;
}

// smem byte offsets (per-CTA total 112896 -> 2 CTAs/SM)
#define AXO  0        // x packed-A [2part][4mt][6ks][512B] : 24576 (lo +12288)
#define A2O  24576    // attn-out packed-A, same shape      : 24576 (lo +12288)
#define WO   49152    // staged weights [2part][12nt][6ks][256B] : 36864 (lo +18432)
#define QO   86016    // q packed-A [2p][4mt][2ks][512]  : 8192 (lo +4096)
#define KO   94208    // k packed-B [2p][8nt][2ks][256]  : 8192 (lo +4096)
#define VO   102400   // v packed-B [2p][4nt][4ks][256]  : 8192 (lo +4096)
#define BQO  110592   // [3][96] f32 qkv bias (q pre-scaled)
#define PBO  111744   // 96 f32
#define INVO 112128   // 96 f32
#define SHO  112512   // 96 f32
#define SMEM_BYTES 112896

template<bool ATOMIC>
__global__ __launch_bounds__(TPB, 2)
void swin_mma_kernel(
    const float* __restrict__ x,
    const float* __restrict__ qkv_b, const float* __restrict__ proj_b,
    const float* __restrict__ bn_g, const float* __restrict__ bn_b,
    const float* __restrict__ bn_m, const float* __restrict__ bn_v,
    float* __restrict__ out, int br)
{
    extern __shared__ unsigned char smc[];
    float* bqs  = (float*)(smc + BQO);
    float* pbs  = (float*)(smc + PBO);
    float* invs = (float*)(smc + INVO);
    float* shs  = (float*)(smc + SHO);

    const int tid = threadIdx.x;
    const int wrp = tid >> 5;
    const int l   = tid & 31;

    const int bid = blockIdx.x;
    const int g   = bid & 127;          // image index inner -> L2 sharing
    const int win = bid >> 7;           // 0..63
    const int wi  = win >> 3;
    const int wj  = win & 7;
    const int b   = g >> 6;
    const int s   = g & 63;

    if (tid < 96) {
        float inv = bn_g[br * 96 + tid] * rsqrtf(bn_v[br * 96 + tid] + 1e-5f);
        invs[tid] = inv;
        shs[tid]  = bn_b[br * 96 + tid] - bn_m[br * 96 + tid] * inv;
        pbs[tid]  = proj_b[br * 96 + tid];
    }
    for (int i = tid; i < 288; i += TPB) {
        int h = i / 96, u = i - h * 96;
        int sub = u >> 5, dim = u & 31;
        float v = qkv_b[br * 288 + sub * 96 + h * 32 + dim];
        if (sub == 0) v *= SCALE;
        bqs[i] = v;
    }

    // stage weights for head 0 (all threads)
    {
        const uint4* src = (const uint4*)(g_wpk + (size_t)(br * 4) * 36864);
        uint4* dst = (uint4*)(smc + WO);
        for (int i = tid; i < 2304; i += TPB) dst[i] = src[i];
    }

    // ---- load x -> packed-A (split bf16) ----------------------------------
    for (int i = tid; i < 6144; i += TPB) {
        int row = i & 63, c = i >> 6;                 // c 0..95
        int p = wi * 8 + (row >> 3), q = wj * 8 + (row & 7);
        float v = x[x_off(br, b, c, s, p, q)];
        __nv_bfloat16 hi = __float2bfloat16(v);
        __nv_bfloat16 lo = __float2bfloat16(v - __bfloat162float(hi));
        int mt = row >> 4, rr = row & 15, ks = c >> 4;
        int ln = ((rr & 7) << 2) | ((c >> 1) & 3);
        int rg = (rr >> 3) | (((c >> 3) & 1) << 1);
        int off = (mt * 6 + ks) * 512 + ln * 16 + rg * 4 + (c & 1) * 2;
        *(__nv_bfloat16*)(smc + AXO + off)         = hi;
        *(__nv_bfloat16*)(smc + AXO + 12288 + off) = lo;
    }
    __syncthreads();

    // ======================= per head ======================================
    for (int h = 0; h < 3; ++h) {
        // ---- GEMM1: [64 tok] x [96 outs(q,k,v of head)] x K=96, all 8 warps
        {
            const int mt = wrp & 3, ng = wrp >> 2;
            float acc[6][4];
            #pragma unroll
            for (int j = 0; j < 6; ++j) {
                int c0 = (ng * 6 + j) * 8 + (l & 3) * 2;
                acc[j][0] = bqs[h * 96 + c0]; acc[j][1] = bqs[h * 96 + c0 + 1];
                acc[j][2] = acc[j][0];        acc[j][3] = acc[j][1];
            }
            #pragma unroll
            for (int ks = 0; ks < 6; ++ks) {
                uint4 ah = *(const uint4*)(smc + AXO + (mt * 6 + ks) * 512 + l * 16);
                uint4 al = *(const uint4*)(smc + AXO + 12288 + (mt * 6 + ks) * 512 + l * 16);
                #pragma unroll
                for (int j = 0; j < 6; ++j) {
                    int nt = ng * 6 + j;
                    uint2 bh = *(const uint2*)(smc + WO + (nt * 6 + ks) * 256 + l * 8);
                    uint2 bl = *(const uint2*)(smc + WO + 18432 + (nt * 6 + ks) * 256 + l * 8);
                    mma16816(acc[j], ah, bh);
                    mma16816(acc[j], ah, bl);
                    mma16816(acc[j], al, bh);
                }
            }
            const int r0 = l >> 2;
            #pragma unroll
            for (int j = 0; j < 6; ++j) {
                int nt = ng * 6 + j;
                #pragma unroll
                for (int j2 = 0; j2 < 2; ++j2) {
                    float v0 = acc[j][2 * j2], v1 = acc[j][2 * j2 + 1];
                    if (nt < 4) {                         // q -> packed-A
                        u32 H, L; packsplit(v0, v1, H, L);
                        int o = QO + (mt * 2 + (nt >> 1)) * 512
                                + l * 16 + (j2 | ((nt & 1) << 1)) * 4;
                        *(u32*)(smc + o)        = H;
                        *(u32*)(smc + o + 4096) = L;
                    } else if (nt < 8) {                  // k -> packed-B
                        u32 H, L; packsplit(v0, v1, H, L);
                        int ntk = nt - 4;
                        int tok8 = mt * 2 + j2;
                        int o = KO + (tok8 * 2 + (ntk >> 1)) * 256
                                + l * 8 + (ntk & 1) * 4;
                        *(u32*)(smc + o)        = H;
                        *(u32*)(smc + o + 4096) = L;
                    } else {                              // v -> packed-B (transposed)
                        int ntv = nt - 8;
                        #pragma unroll
                        for (int t2 = 0; t2 < 2; ++t2) {
                            int d = ntv * 8 + (l & 3) * 2 + t2;
                            float vv = t2 ? v1 : v0;
                            __nv_bfloat16 hi = __float2bfloat16(vv);
                            __nv_bfloat16 lo = __float2bfloat16(vv - __bfloat162float(hi));
                            int o = VO + ((d >> 3) * 4 + mt) * 256
                                    + (((d & 7) << 2) | ((r0 >> 1) & 3)) * 8
                                    + j2 * 4 + (r0 & 1) * 2;
                            *(__nv_bfloat16*)(smc + o)        = hi;
                            *(__nv_bfloat16*)(smc + o + 4096) = lo;
                        }
                    }
                }
            }
        }
        __syncthreads();

        if (wrp < 4) {
            // =============== attention, fully in registers ==================
            const int mt = wrp;
            const int r0 = l >> 2;
            const int n0 = mt * 16 + r0;

            // bias prefetch (LDG.64, high MLP)
            const float* gb = g_bias + (br * 3 + h) * 4096;
            float2 bs0[8], bs1[8];
            #pragma unroll
            for (int j = 0; j < 8; ++j) {
                int m0 = j * 8 + (l & 3) * 2;
                bs0[j] = __ldg((const float2*)(gb + n0 * 64 + m0));
                bs1[j] = __ldg((const float2*)(gb + (n0 + 8) * 64 + m0));
            }

            // q A-frags
            uint4 qh[2], ql[2];
            #pragma unroll
            for (int ks = 0; ks < 2; ++ks) {
                qh[ks] = *(const uint4*)(smc + QO + (mt * 2 + ks) * 512 + l * 16);
                ql[ks] = *(const uint4*)(smc + QO + 4096 + (mt * 2 + ks) * 512 + l * 16);
            }

            // QK^T
            float acc[8][4];
            #pragma unroll
            for (int j = 0; j < 8; ++j)
                acc[j][0] = acc[j][1] = acc[j][2] = acc[j][3] = 0.f;
            #pragma unroll
            for (int ks = 0; ks < 2; ++ks) {
                #pragma unroll
                for (int j = 0; j < 8; ++j) {
                    uint2 bh = *(const uint2*)(smc + KO + (j * 2 + ks) * 256 + l * 8);
                    uint2 bl = *(const uint2*)(smc + KO + 4096 + (j * 2 + ks) * 256 + l * 8);
                    mma16816(acc[j], qh[ks], bh);
                    mma16816(acc[j], qh[ks], bl);
                    mma16816(acc[j], ql[ks], bh);
                }
            }
            #pragma unroll
            for (int j = 0; j < 8; ++j) {
                acc[j][0] += bs0[j].x; acc[j][1] += bs0[j].y;
                acc[j][2] += bs1[j].x; acc[j][3] += bs1[j].y;
            }

            // softmax: rows r0 (c0,c1) and r0+8 (c2,c3), quad-shuffle reduce
            float mx0 = -1e30f, mx1 = -1e30f;
            #pragma unroll
            for (int j = 0; j < 8; ++j) {
                mx0 = fmaxf(mx0, fmaxf(acc[j][0], acc[j][1]));
                mx1 = fmaxf(mx1, fmaxf(acc[j][2], acc[j][3]));
            }
            mx0 = fmaxf(mx0, __shfl_xor_sync(0xffffffff, mx0, 1));
            mx0 = fmaxf(mx0, __shfl_xor_sync(0xffffffff, mx0, 2));
            mx1 = fmaxf(mx1, __shfl_xor_sync(0xffffffff, mx1, 1));
            mx1 = fmaxf(mx1, __shfl_xor_sync(0xffffffff, mx1, 2));
            float s0 = 0.f, s1 = 0.f;
            #pragma unroll
            for (int j = 0; j < 8; ++j) {
                acc[j][0] = __expf(acc[j][0] - mx0); s0 += acc[j][0];
                acc[j][1] = __expf(acc[j][1] - mx0); s0 += acc[j][1];
                acc[j][2] = __expf(acc[j][2] - mx1); s1 += acc[j][2];
                acc[j][3] = __expf(acc[j][3] - mx1); s1 += acc[j][3];
            }
            s0 += __shfl_xor_sync(0xffffffff, s0, 1);
            s0 += __shfl_xor_sync(0xffffffff, s0, 2);
            s1 += __shfl_xor_sync(0xffffffff, s1, 1);
            s1 += __shfl_xor_sync(0xffffffff, s1, 2);
            float rs0 = 1.f / s0, rs1 = 1.f / s1;
            #pragma unroll
            for (int j = 0; j < 8; ++j) {
                acc[j][0] *= rs0; acc[j][1] *= rs0;
                acc[j][2] *= rs1; acc[j][3] *= rs1;
            }

            // pack P -> A-frags in registers (acc layout == A-frag layout)
            uint4 ph[4], pl[4];
            #pragma unroll
            for (int ks = 0; ks < 4; ++ks) {
                packsplit(acc[2 * ks][0],     acc[2 * ks][1],     ph[ks].x, pl[ks].x);
                packsplit(acc[2 * ks][2],     acc[2 * ks][3],     ph[ks].y, pl[ks].y);
                packsplit(acc[2 * ks + 1][0], acc[2 * ks + 1][1], ph[ks].z, pl[ks].z);
                packsplit(acc[2 * ks + 1][2], acc[2 * ks + 1][3], ph[ks].w, pl[ks].w);
            }

            // AV
            float av[4][4];
            #pragma unroll
            for (int nt = 0; nt < 4; ++nt)
                av[nt][0] = av[nt][1] = av[nt][2] = av[nt][3] = 0.f;
            #pragma unroll
            for (int ks = 0; ks < 4; ++ks) {
                #pragma unroll
                for (int nt = 0; nt < 4; ++nt) {
                    uint2 vh = *(const uint2*)(smc + VO + (nt * 4 + ks) * 256 + l * 8);
                    uint2 vl = *(const uint2*)(smc + VO + 4096 + (nt * 4 + ks) * 256 + l * 8);
                    mma16816(av[nt], ph[ks], vh);
                    mma16816(av[nt], ph[ks], vl);
                    mma16816(av[nt], pl[ks], vh);
                }
            }

            // attn-out -> A2 packed-A (split bf16)
            #pragma unroll
            for (int nt = 0; nt < 4; ++nt) {
                int ksa  = 2 * h + (nt >> 1);
                int rghi = (nt & 1) << 1;
                #pragma unroll
                for (int j2 = 0; j2 < 2; ++j2) {
                    u32 H, L;
                    packsplit(av[nt][2 * j2], av[nt][2 * j2 + 1], H, L);
                    int o = A2O + (mt * 6 + ksa) * 512 + l * 16 + (j2 | rghi) * 4;
                    *(u32*)(smc + o)         = H;
                    *(u32*)(smc + o + 12288) = L;
                }
            }
        } else {
            // =============== stage next matrix's weights (h+1; 3 == proj) ==
            const uint4* src = (const uint4*)(g_wpk + (size_t)(br * 4 + h + 1) * 36864);
            uint4* dst = (uint4*)(smc + WO);
            for (int i = tid - 128; i < 2304; i += 128) dst[i] = src[i];
        }
        __syncthreads();
    }

    // ======================= proj + BN + LeakyReLU =========================
    {
        const int mt = wrp & 3, ng = wrp >> 2;
        float acc[6][4];
        #pragma unroll
        for (int j = 0; j < 6; ++j) {
            int c0 = (ng * 6 + j) * 8 + (l & 3) * 2;
            acc[j][0] = pbs[c0]; acc[j][1] = pbs[c0 + 1];
            acc[j][2] = pbs[c0]; acc[j][3] = pbs[c0 + 1];
        }
        #pragma unroll
        for (int ks = 0; ks < 6; ++ks) {
            uint4 ah = *(const uint4*)(smc + A2O + (mt * 6 + ks) * 512 + l * 16);
            uint4 al = *(const uint4*)(smc + A2O + 12288 + (mt * 6 + ks) * 512 + l * 16);
            #pragma unroll
            for (int j = 0; j < 6; ++j) {
                int nt = ng * 6 + j;
                uint2 bh = *(const uint2*)(smc + WO + (nt * 6 + ks) * 256 + l * 8);
                uint2 bl = *(const uint2*)(smc + WO + 18432 + (nt * 6 + ks) * 256 + l * 8);
                mma16816(acc[j], ah, bh);
                mma16816(acc[j], ah, bl);
                mma16816(acc[j], al, bh);
            }
        }
        const int r0 = l >> 2;
        #pragma unroll
        for (int j = 0; j < 6; ++j) {
            int c0 = (ng * 6 + j) * 8 + (l & 3) * 2;
            #pragma unroll
            for (int j2 = 0; j2 < 2; ++j2) {
                int tl = mt * 16 + r0 + 8 * j2;
                int p = wi * 8 + (tl >> 3);
                int q = wj * 8 + (tl & 7);
                #pragma unroll
                for (int t2 = 0; t2 < 2; ++t2) {
                    int co = c0 + t2;
                    float v = acc[j][2 * j2 + t2];
                    float yn = v * invs[co] + shs[co];
                    yn = (yn >= 0.f) ? yn : 0.01f * yn;
                    int off = x_off(br, b, co, s, p, q);
                    if (ATOMIC) atomicAdd(&out[off], yn);
                    else        out[off] = yn;
                }
            }
        }
    }
}

extern "C" void kernel_launch(void* const* d_in, const int* in_sizes, int n_in,
                              void* d_out, int out_size)
{
    (void)in_sizes; (void)n_in; (void)out_size;
    const float* x         = (const float*)d_in[0];
    const float* qkv_w     = (const float*)d_in[1];
    const float* qkv_b     = (const float*)d_in[2];
    const float* proj_w    = (const float*)d_in[3];
    const float* proj_b    = (const float*)d_in[4];
    const float* rpb_table = (const float*)d_in[5];
    const float* bn_g      = (const float*)d_in[6];
    const float* bn_b      = (const float*)d_in[7];
    const float* bn_m      = (const float*)d_in[8];
    const float* bn_v      = (const float*)d_in[9];
    const int*   rpb_index = (const int*)d_in[10];
    float* out = (float*)d_out;

    wprep<<<576, 256>>>(qkv_w, proj_w, rpb_table, rpb_index);

    cudaFuncSetAttribute(swin_mma_kernel<false>,
                         cudaFuncAttributeMaxDynamicSharedMemorySize, SMEM_BYTES);
    cudaFuncSetAttribute(swin_mma_kernel<true>,
                         cudaFuncAttributeMaxDynamicSharedMemorySize, SMEM_BYTES);

    // Branch 0: plain stores (full output coverage kills 0xAA poison)
    swin_mma_kernel<false><<<8192, TPB, SMEM_BYTES>>>(
        x, qkv_b, proj_b, bn_g, bn_b, bn_m, bn_v, out, 0);
    // Branches 1 & 2: accumulate
    swin_mma_kernel<true><<<8192, TPB, SMEM_BYTES>>>(
        x, qkv_b, proj_b, bn_g, bn_b, bn_m, bn_v, out, 1);
    swin_mma_kernel<true><<<8192, TPB, SMEM_BYTES>>>(
        x, qkv_b, proj_b, bn_g, bn_b, bn_m, bn_v, out, 2);
}